// round 8
// baseline (speedup 1.0000x reference)
#include <cuda_runtime.h>
#include <cuda_fp16.h>
#include <cstdint>

// -------------------- fp16 scratch (device globals) ------------------------
__device__ __half h_x  [2097152];   // [2,2048,512]
__device__ __half h_x1 [2097152];
__device__ __half h_wqv[524288];    // [512,1024]
__device__ __half h_wk [262144];    // [512,512]
__device__ __half h_wout[262144];   // [512,512]
__device__ __half g_q[2097152];     // [b,h,n,d]
__device__ __half g_k[2097152];     // [b,h,m,d]
__device__ __half g_v[2097152];     // [b,h,m,d]
__device__ __half g_o[2097152];     // [b,n,512]

__device__ __forceinline__ uint32_t smaddr(const void* p) {
    return (uint32_t)__cvta_generic_to_shared(p);
}
#define CP16(dst_u32, src_ptr) \
    asm volatile("cp.async.cg.shared.global [%0], [%1], 16;\n" \
                 :: "r"(dst_u32), "l"(src_ptr))
#define CPCOMMIT() asm volatile("cp.async.commit_group;\n" ::)
#define CPWAIT0()  asm volatile("cp.async.wait_group 0;\n" ::)
#define CPWAIT1()  asm volatile("cp.async.wait_group 1;\n" ::)

__device__ __forceinline__ float ex2f(float x) {
    float r;
    asm("ex2.approx.ftz.f32 %0, %1;" : "=f"(r) : "f"(x));
    return r;
}
__device__ __forceinline__ uint32_t pk(float a, float b) {
    __half2 h = __floats2half2_rn(a, b);
    return *reinterpret_cast<uint32_t*>(&h);
}
__device__ __forceinline__ void mma_h(float c[4],
                                      uint32_t a0, uint32_t a1, uint32_t a2, uint32_t a3,
                                      uint32_t b0, uint32_t b1) {
    asm volatile(
        "mma.sync.aligned.m16n8k16.row.col.f32.f16.f16.f32 "
        "{%0,%1,%2,%3}, {%4,%5,%6,%7}, {%8,%9}, {%0,%1,%2,%3};\n"
        : "+f"(c[0]), "+f"(c[1]), "+f"(c[2]), "+f"(c[3])
        : "r"(a0), "r"(a1), "r"(a2), "r"(a3), "r"(b0), "r"(b1));
}
__device__ __forceinline__ void ldsm4(uint32_t& r0, uint32_t& r1,
                                      uint32_t& r2, uint32_t& r3, uint32_t addr) {
    asm volatile(
        "ldmatrix.sync.aligned.m8n8.x4.shared.b16 {%0,%1,%2,%3}, [%4];\n"
        : "=r"(r0), "=r"(r1), "=r"(r2), "=r"(r3) : "r"(addr));
}
__device__ __forceinline__ void ldsm4t(uint32_t& r0, uint32_t& r1,
                                       uint32_t& r2, uint32_t& r3, uint32_t addr) {
    asm volatile(
        "ldmatrix.sync.aligned.m8n8.x4.trans.shared.b16 {%0,%1,%2,%3}, [%4];\n"
        : "=r"(r0), "=r"(r1), "=r"(r2), "=r"(r3) : "r"(addr));
}

// -------------------- fp32 -> fp16 conversion ------------------------------
__global__ void __launch_bounds__(256)
convert_k(const float* __restrict__ x, const float* __restrict__ x1,
          const float* __restrict__ wqv, const float* __restrict__ wk,
          const float* __restrict__ wout)
{
    const float* src;
    __half* dst;
    int nq;
    switch (blockIdx.y) {
        case 0: src = x;    dst = h_x;    nq = 524288; break;
        case 1: src = x1;   dst = h_x1;   nq = 524288; break;
        case 2: src = wqv;  dst = h_wqv;  nq = 131072; break;
        case 3: src = wk;   dst = h_wk;   nq = 65536;  break;
        default: src = wout; dst = h_wout; nq = 65536; break;
    }
    const int i = blockIdx.x * 256 + threadIdx.x;
    if (i < nq) {
        float4 v = reinterpret_cast<const float4*>(src)[i];
        uint2 o = { pk(v.x, v.y), pk(v.z, v.w) };
        reinterpret_cast<uint2*>(dst)[i] = o;
    }
}

// ---------------------------------------------------------------------------
// fp16 GEMM: CTA tile 128 x TN, 256 thr (8 warps 4x2, warp tile 32 x TN/2),
// K chunks 32, 2-stage cp.async.
// MODE 0 (TN=128): h_x@h_wqv -> g_q/g_v;  1 (TN=64): h_x1@h_wk -> g_k;
// MODE 2 (TN=64): g_o@h_wout + b -> out.
// ---------------------------------------------------------------------------
#define HA_LD 20

template <int MODE, int TN>
__global__ void __launch_bounds__(256, 2)
gemm_h(int ncols, const float* __restrict__ bias, float* __restrict__ Cout)
{
    constexpr int HB_LD = (TN == 128) ? 68 : 36;
    constexpr int STAGE = 128 * HA_LD + 32 * HB_LD;
    constexpr int NT = TN / 16;          // n-tiles per warp
    extern __shared__ uint32_t sm[];
    const int tid  = threadIdx.x;
    const int lane = tid & 31;
    const int w    = tid >> 5;
    const int g    = lane >> 2;
    const int tg   = lane & 3;
    const int wr   = w >> 1;
    const int wc   = w & 1;
    const int row0 = blockIdx.y * 128;
    const int col0 = blockIdx.x * TN;

    const __half* Ap = (MODE == 0) ? h_x : (MODE == 1) ? h_x1 : g_o;
    const __half* Wp = (MODE == 0) ? h_wqv : (MODE == 1) ? h_wk : h_wout;

    uint32_t* const AsS[2] = { sm, sm + STAGE };
    uint32_t* const BsS[2] = { sm + 128 * HA_LD, sm + STAGE + 128 * HA_LD };

    float acc[2][NT][4] = {};

#pragma unroll
    for (int i = 0; i < 2; i++) {
        const int idx = tid + i * 256;
        const int r = idx >> 2, q = idx & 3;
        CP16(smaddr(&AsS[0][r * HA_LD + q * 4]),
             Ap + (size_t)(row0 + r) * 512 + q * 8);
    }
#pragma unroll
    for (int i = 0; i < TN / 64; i++) {
        const int idx = tid + i * 256;
        const int r = idx / (TN / 8), q = idx % (TN / 8);
        CP16(smaddr(&BsS[0][r * HB_LD + q * 4]),
             Wp + (size_t)r * ncols + col0 + q * 8);
    }
    CPCOMMIT();

    for (int ch = 0; ch < 16; ch++) {
        CPWAIT0();
        __syncthreads();
        if (ch < 15) {
            const int k0 = (ch + 1) * 32;
            const int s  = (ch + 1) & 1;
#pragma unroll
            for (int i = 0; i < 2; i++) {
                const int idx = tid + i * 256;
                const int r = idx >> 2, q = idx & 3;
                CP16(smaddr(&AsS[s][r * HA_LD + q * 4]),
                     Ap + (size_t)(row0 + r) * 512 + k0 + q * 8);
            }
#pragma unroll
            for (int i = 0; i < TN / 64; i++) {
                const int idx = tid + i * 256;
                const int r = idx / (TN / 8), q = idx % (TN / 8);
                CP16(smaddr(&BsS[s][r * HB_LD + q * 4]),
                     Wp + (size_t)(k0 + r) * ncols + col0 + q * 8);
            }
            CPCOMMIT();
        }
        const uint32_t* as = AsS[ch & 1];
        const __half* bsh = reinterpret_cast<const __half*>(BsS[ch & 1]);

#pragma unroll
        for (int kt = 0; kt < 2; kt++) {
            uint32_t a[2][4];
#pragma unroll
            for (int mt = 0; mt < 2; mt++) {
                const int r = wr * 32 + mt * 16;
                a[mt][0] = as[(r + g) * HA_LD + kt * 8 + tg];
                a[mt][1] = as[(r + g + 8) * HA_LD + kt * 8 + tg];
                a[mt][2] = as[(r + g) * HA_LD + kt * 8 + tg + 4];
                a[mt][3] = as[(r + g + 8) * HA_LD + kt * 8 + tg + 4];
            }
            uint32_t bfr[NT][2];
#pragma unroll
            for (int ntp = 0; ntp < NT / 2; ntp++) {
                const int kr   = kt * 16 + ((lane >> 3) & 1) * 8 + (lane & 7);
                const int ncol = wc * (TN / 2) + (ntp * 2 + (lane >> 4)) * 8;
                ldsm4t(bfr[ntp * 2][0], bfr[ntp * 2][1],
                       bfr[ntp * 2 + 1][0], bfr[ntp * 2 + 1][1],
                       smaddr(&bsh[kr * (HB_LD * 2) + ncol]));
            }
#pragma unroll
            for (int nt = 0; nt < NT; nt++)
#pragma unroll
                for (int mt = 0; mt < 2; mt++)
                    mma_h(acc[mt][nt], a[mt][0], a[mt][1], a[mt][2], a[mt][3],
                          bfr[nt][0], bfr[nt][1]);
        }
    }

#pragma unroll
    for (int mt = 0; mt < 2; mt++) {
#pragma unroll
        for (int nt = 0; nt < NT; nt++) {
#pragma unroll
            for (int half = 0; half < 2; half++) {
                const int row = row0 + wr * 32 + mt * 16 + g + half * 8;
                const int col = col0 + wc * (TN / 2) + nt * 8 + 2 * tg;
                const float v0 = acc[mt][nt][half * 2 + 0];
                const float v1 = acc[mt][nt][half * 2 + 1];
                const int b = row >> 11, n = row & 2047;
                if (MODE == 0) {
                    __half* dst;
                    if (col < 512) {
                        const int h = col >> 6, d = col & 63;
                        dst = &g_q[((size_t)(b * 8 + h) * 2048 + n) * 64 + d];
                    } else {
                        const int c2 = col - 512;
                        const int h = c2 >> 6, d = c2 & 63;
                        dst = &g_v[((size_t)(b * 8 + h) * 2048 + n) * 64 + d];
                    }
                    *reinterpret_cast<uint32_t*>(dst) = pk(v0, v1);
                } else if (MODE == 1) {
                    const int h = col >> 6, d = col & 63;
                    __half* dst = &g_k[((size_t)(b * 8 + h) * 2048 + n) * 64 + d];
                    *reinterpret_cast<uint32_t*>(dst) = pk(v0, v1);
                } else {
                    float* dst = &Cout[(size_t)row * 512 + col];
                    *reinterpret_cast<float2*>(dst) =
                        make_float2(v0 + bias[col], v1 + bias[col + 1]);
                }
            }
        }
    }
}

// ---------------------------------------------------------------------------
// Fused attention, fp16 MMA, 3-stage cp.async pipeline (distance-2 prefetch).
// CTA = (b,h,128 q-rows), 256 thr (8 warps x 16 rows). K/V chunks 32 m-rows +
// attn_mat chunk (128x32 f32). P in registers (FA2 identity).
// smem u32: Qs[128][36] | Ks[3][32][36] | Vs[3][32][36] | Am[3][128][36]
//   = 4608 + 3456 + 3456 + 13824 = 25344 u32 = 101,376 B -> occupancy 2.
// ---------------------------------------------------------------------------
#define AQ_LD 36
#define ATT_SMEM_W (128 * AQ_LD + 6 * 32 * AQ_LD + 3 * 128 * AQ_LD)

__global__ void __launch_bounds__(256, 2)
attn_h(const float* __restrict__ amat,
       const float* __restrict__ dots_para,
       const float* __restrict__ mat_para)
{
    extern __shared__ uint32_t sm[];
    uint32_t* const Qs = sm;                              // 128*36
    uint32_t* const Ks0 = sm + 128 * AQ_LD;               // 3 x 32*36
    uint32_t* const Vs0 = Ks0 + 3 * 32 * AQ_LD;           // 3 x 32*36
    uint32_t* const Am0 = Vs0 + 3 * 32 * AQ_LD;           // 3 x 128*36

    const int tid  = threadIdx.x;
    const int lane = tid & 31;
    const int w    = tid >> 5;
    const int g    = lane >> 2;
    const int tg   = lane & 3;
    const int b  = blockIdx.z, h = blockIdx.y;
    const int n0 = blockIdx.x * 128;

    const float qscale = 0.125f * dots_para[0] * 1.44269504f;
    const float mp = mat_para[0] * 1.44269504f;

    const size_t qbase  = ((size_t)(b * 8 + h) * 2048 + n0) * 64;
    const size_t kvbase = (size_t)(b * 8 + h) * 2048 * 64;
    const size_t abase  = ((size_t)(b * 8 + h) * 2048 + n0) * 2048;

    // group 0: Q + chunk 0;  group 1: chunk 1
#pragma unroll
    for (int i = 0; i < 4; i++) {
        const int idx = tid + i * 256;
        const int r = idx >> 3, q = idx & 7;
        CP16(smaddr(&Qs[r * AQ_LD + q * 4]), g_q + qbase + (size_t)r * 64 + q * 8);
    }
#pragma unroll
    for (int pre = 0; pre < 2; pre++) {
        const size_t m1 = (size_t)pre * 32;
        uint32_t* Ks = Ks0 + pre * 32 * AQ_LD;
        uint32_t* Vs = Vs0 + pre * 32 * AQ_LD;
        uint32_t* Am = Am0 + pre * 128 * AQ_LD;
        {
            const int r = tid >> 3, q = tid & 7;
            CP16(smaddr(&Ks[r * AQ_LD + q * 4]), g_k + kvbase + (m1 + r) * 64 + q * 8);
            CP16(smaddr(&Vs[r * AQ_LD + q * 4]), g_v + kvbase + (m1 + r) * 64 + q * 8);
        }
#pragma unroll
        for (int i = 0; i < 4; i++) {
            const int idx = tid + i * 256;
            const int r = idx >> 3, c = (idx & 7) * 4;
            CP16(smaddr(&Am[r * AQ_LD + c]), amat + abase + (size_t)r * 2048 + m1 + c);
        }
        CPCOMMIT();
    }

    float O[8][4] = {};
    float rl0 = 0.f, rl1 = 0.f;
    const int rowA = w * 16 + g;

    for (int ch = 0; ch < 64; ch++) {
        if (ch == 63) { CPWAIT0(); } else { CPWAIT1(); }
        __syncthreads();
        if (ch < 62) {
            const size_t m1 = (size_t)(ch + 2) * 32;
            const int s = (ch + 2) % 3;
            uint32_t* Ksw = Ks0 + s * 32 * AQ_LD;
            uint32_t* Vsw = Vs0 + s * 32 * AQ_LD;
            uint32_t* Amw = Am0 + s * 128 * AQ_LD;
            {
                const int r = tid >> 3, q = tid & 7;
                CP16(smaddr(&Ksw[r * AQ_LD + q * 4]),
                     g_k + kvbase + (m1 + r) * 64 + q * 8);
                CP16(smaddr(&Vsw[r * AQ_LD + q * 4]),
                     g_v + kvbase + (m1 + r) * 64 + q * 8);
            }
#pragma unroll
            for (int i = 0; i < 4; i++) {
                const int idx = tid + i * 256;
                const int r = idx >> 3, c = (idx & 7) * 4;
                CP16(smaddr(&Amw[r * AQ_LD + c]),
                     amat + abase + (size_t)r * 2048 + m1 + c);
            }
            CPCOMMIT();
        }
        const int st = ch % 3;
        const __half* Qsh = reinterpret_cast<const __half*>(Qs);
        const __half* Ksh = reinterpret_cast<const __half*>(Ks0 + st * 32 * AQ_LD);
        const __half* Vsh = reinterpret_cast<const __half*>(Vs0 + st * 32 * AQ_LD);
        const float*  Am  = reinterpret_cast<const float*>(Am0 + st * 128 * AQ_LD);

        // S = Q @ K^T  (per warp 16 x 32), frags via ldmatrix.x4
        float S[4][4] = {};
#pragma unroll
        for (int kt = 0; kt < 4; kt++) {
            uint32_t aq0, aq1, aq2, aq3;
            {
                const int mr = w * 16 + (lane & 15);
                const int kc = kt * 16 + (lane >> 4) * 8;
                ldsm4(aq0, aq1, aq2, aq3, smaddr(&Qsh[mr * (AQ_LD * 2) + kc]));
            }
#pragma unroll
            for (int ntp = 0; ntp < 2; ntp++) {
                uint32_t kb0, kb1, kb2, kb3;
                const int nr = ntp * 16 + ((lane >> 4) & 1) * 8 + (lane & 7);
                const int kc = kt * 16 + ((lane >> 3) & 1) * 8;
                ldsm4(kb0, kb1, kb2, kb3, smaddr(&Ksh[nr * (AQ_LD * 2) + kc]));
                mma_h(S[ntp * 2],     aq0, aq1, aq2, aq3, kb0, kb1);
                mma_h(S[ntp * 2 + 1], aq0, aq1, aq2, aq3, kb2, kb3);
            }
        }

        // bias (smem-staged amat) + exp -> P packed as PV A-fragments
        uint32_t pva[2][4];
#pragma unroll
        for (int nt = 0; nt < 4; nt++) {
            const int acol = nt * 8 + 2 * tg;
            const float2 amA = *reinterpret_cast<const float2*>(
                &Am[rowA * AQ_LD + acol]);
            const float2 amB = *reinterpret_cast<const float2*>(
                &Am[(rowA + 8) * AQ_LD + acol]);
            const float p0 = ex2f(S[nt][0] * qscale + amA.x * mp);
            const float p1 = ex2f(S[nt][1] * qscale + amA.y * mp);
            const float p2 = ex2f(S[nt][2] * qscale + amB.x * mp);
            const float p3 = ex2f(S[nt][3] * qscale + amB.y * mp);
            rl0 += p0 + p1;
            rl1 += p2 + p3;
            pva[nt >> 1][(nt & 1) * 2 + 0] = pk(p0, p1);
            pva[nt >> 1][(nt & 1) * 2 + 1] = pk(p2, p3);
        }

        // O += P @ V  (V B-frags via ldmatrix.trans on row-major [m][d])
#pragma unroll
        for (int j = 0; j < 2; j++) {
            uint32_t vb[8][2];
#pragma unroll
            for (int ntp = 0; ntp < 4; ntp++) {
                const int mr = j * 16 + ((lane >> 3) & 1) * 8 + (lane & 7);
                const int dc = (ntp * 2 + (lane >> 4)) * 8;
                ldsm4t(vb[ntp * 2][0], vb[ntp * 2][1],
                       vb[ntp * 2 + 1][0], vb[ntp * 2 + 1][1],
                       smaddr(&Vsh[mr * (AQ_LD * 2) + dc]));
            }
#pragma unroll
            for (int nt = 0; nt < 8; nt++)
                mma_h(O[nt], pva[j][0], pva[j][1], pva[j][2], pva[j][3],
                      vb[nt][0], vb[nt][1]);
        }
    }

    // quad-reduce row sums, normalize, store fp16
#pragma unroll
    for (int off = 1; off <= 2; off <<= 1) {
        rl0 += __shfl_xor_sync(0xffffffffu, rl0, off);
        rl1 += __shfl_xor_sync(0xffffffffu, rl1, off);
    }
    const float inv0 = 1.0f / rl0;
    const float inv1 = 1.0f / rl1;
    const int grow = n0 + rowA;
#pragma unroll
    for (int nt = 0; nt < 8; nt++) {
        const int col = h * 64 + nt * 8 + 2 * tg;
        *reinterpret_cast<uint32_t*>(&g_o[((size_t)b * 2048 + grow) * 512 + col]) =
            pk(O[nt][0] * inv0, O[nt][1] * inv0);
        *reinterpret_cast<uint32_t*>(&g_o[((size_t)b * 2048 + grow + 8) * 512 + col]) =
            pk(O[nt][2] * inv1, O[nt][3] * inv1);
    }
}

// ---------------------------------------------------------------------------
extern "C" void kernel_launch(void* const* d_in, const int* in_sizes, int n_in,
                              void* d_out, int out_size)
{
    const float* x    = (const float*)d_in[0];
    const float* x1   = (const float*)d_in[1];
    const float* amat = (const float*)d_in[2];
    const float* dp   = (const float*)d_in[3];
    const float* mp   = (const float*)d_in[4];
    const float* Wqv  = (const float*)d_in[5];
    const float* Wk   = (const float*)d_in[6];
    const float* Wout = (const float*)d_in[7];
    const float* bout = (const float*)d_in[8];
    float* out = (float*)d_out;

    const int gsmem128 = 2 * (128 * HA_LD + 32 * 68) * (int)sizeof(uint32_t); // 37,888
    const int gsmem64  = 2 * (128 * HA_LD + 32 * 36) * (int)sizeof(uint32_t); // 29,696
    const int asmem    = ATT_SMEM_W * (int)sizeof(uint32_t);                  // 101,376
    cudaFuncSetAttribute((const void*)attn_h,
                         cudaFuncAttributeMaxDynamicSharedMemorySize, asmem);

    // fp32 -> fp16 staging
    convert_k<<<dim3(2048, 5), 256>>>(x, x1, Wqv, Wk, Wout);
    // q,v projection: [4096,512] @ [512,1024], 128x128 tiles -> 256 CTAs
    gemm_h<0, 128><<<dim3(8, 32), 256, gsmem128>>>(1024, nullptr, nullptr);
    // k projection: [4096,512] @ [512,512], 128x64 tiles -> 256 CTAs
    gemm_h<1, 64><<<dim3(8, 32), 256, gsmem64>>>(512, nullptr, nullptr);
    // fused attention (3-stage pipeline)
    attn_h<<<dim3(16, 8, 2), 256, asmem>>>(amat, dp, mp);
    // output projection + bias, 128x64 tiles -> 256 CTAs
    gemm_h<2, 64><<<dim3(8, 32), 256, gsmem64>>>(512, bout, out);
}

// round 9
// speedup vs baseline: 1.4469x; 1.4469x over previous
#include <cuda_runtime.h>
#include <cuda_fp16.h>
#include <cstdint>

// -------------------- fp16 scratch (device globals) ------------------------
__device__ __half h_x  [2097152];   // [2,2048,512]
__device__ __half h_x1 [2097152];
__device__ __half h_wqv[524288];    // [512,1024]
__device__ __half h_wk [262144];    // [512,512]
__device__ __half h_wout[262144];   // [512,512]
__device__ __half g_q[2097152];     // [b,h,n,d]
__device__ __half g_k[2097152];     // [b,h,m,d]
__device__ __half g_v[2097152];     // [b,h,m,d]
__device__ __half g_o[2097152];     // [b,n,512]

__device__ __forceinline__ uint32_t smaddr(const void* p) {
    return (uint32_t)__cvta_generic_to_shared(p);
}
#define CP16(dst_u32, src_ptr) \
    asm volatile("cp.async.cg.shared.global [%0], [%1], 16;\n" \
                 :: "r"(dst_u32), "l"(src_ptr))
#define CPCOMMIT() asm volatile("cp.async.commit_group;\n" ::)
#define CPWAIT0()  asm volatile("cp.async.wait_group 0;\n" ::)

__device__ __forceinline__ float ex2f(float x) {
    float r;
    asm("ex2.approx.ftz.f32 %0, %1;" : "=f"(r) : "f"(x));
    return r;
}
__device__ __forceinline__ uint32_t pk(float a, float b) {
    __half2 h = __floats2half2_rn(a, b);
    return *reinterpret_cast<uint32_t*>(&h);
}
__device__ __forceinline__ void mma_h(float c[4],
                                      uint32_t a0, uint32_t a1, uint32_t a2, uint32_t a3,
                                      uint32_t b0, uint32_t b1) {
    asm volatile(
        "mma.sync.aligned.m16n8k16.row.col.f32.f16.f16.f32 "
        "{%0,%1,%2,%3}, {%4,%5,%6,%7}, {%8,%9}, {%0,%1,%2,%3};\n"
        : "+f"(c[0]), "+f"(c[1]), "+f"(c[2]), "+f"(c[3])
        : "r"(a0), "r"(a1), "r"(a2), "r"(a3), "r"(b0), "r"(b1));
}
__device__ __forceinline__ void ldsm4(uint32_t& r0, uint32_t& r1,
                                      uint32_t& r2, uint32_t& r3, uint32_t addr) {
    asm volatile(
        "ldmatrix.sync.aligned.m8n8.x4.shared.b16 {%0,%1,%2,%3}, [%4];\n"
        : "=r"(r0), "=r"(r1), "=r"(r2), "=r"(r3) : "r"(addr));
}
__device__ __forceinline__ void ldsm4t(uint32_t& r0, uint32_t& r1,
                                       uint32_t& r2, uint32_t& r3, uint32_t addr) {
    asm volatile(
        "ldmatrix.sync.aligned.m8n8.x4.trans.shared.b16 {%0,%1,%2,%3}, [%4];\n"
        : "=r"(r0), "=r"(r1), "=r"(r2), "=r"(r3) : "r"(addr));
}

// -------------------- fp32 -> fp16 conversion ------------------------------
__global__ void __launch_bounds__(256)
convert_k(const float* __restrict__ x, const float* __restrict__ x1,
          const float* __restrict__ wqv, const float* __restrict__ wk,
          const float* __restrict__ wout)
{
    const float* src;
    __half* dst;
    int nq;
    switch (blockIdx.y) {
        case 0: src = x;    dst = h_x;    nq = 524288; break;
        case 1: src = x1;   dst = h_x1;   nq = 524288; break;
        case 2: src = wqv;  dst = h_wqv;  nq = 131072; break;
        case 3: src = wk;   dst = h_wk;   nq = 65536;  break;
        default: src = wout; dst = h_wout; nq = 65536; break;
    }
    const int i = blockIdx.x * 256 + threadIdx.x;
    if (i < nq) {
        float4 v = reinterpret_cast<const float4*>(src)[i];
        uint2 o = { pk(v.x, v.y), pk(v.z, v.w) };
        reinterpret_cast<uint2*>(dst)[i] = o;
    }
}

// ---------------------------------------------------------------------------
// fp16 GEMM: CTA tile 128x128, 256 thr (8 warps 4x2, warp 32x64), K chunks 32,
// 2-stage cp.async. (proven round-6/7 structure)
// MODE 3: fused qv+k projection — blockIdx.x<8: x@W_qv cols; else x1@W_k.
// MODE 2: g_o@h_wout + bias -> out.
// ---------------------------------------------------------------------------
#define HA_LD 20
#define HB_LD 68
#define H_STAGE (128 * HA_LD + 32 * HB_LD)   // 4736 u32

template <int MODE>
__global__ void __launch_bounds__(256, 2)
gemm_h(const float* __restrict__ bias, float* __restrict__ Cout)
{
    extern __shared__ uint32_t sm[];
    const int tid  = threadIdx.x;
    const int lane = tid & 31;
    const int w    = tid >> 5;
    const int g    = lane >> 2;
    const int tg   = lane & 3;
    const int wr   = w >> 1;
    const int wc   = w & 1;
    const int row0 = blockIdx.y * 128;

    bool isQV = true;
    int col0, ncols;
    const __half* Ap;
    const __half* Wp;
    if (MODE == 3) {
        isQV = (blockIdx.x < 8);
        col0 = isQV ? blockIdx.x * 128 : (blockIdx.x - 8) * 128;
        ncols = isQV ? 1024 : 512;
        Ap = isQV ? h_x : h_x1;
        Wp = isQV ? h_wqv : h_wk;
    } else {
        col0 = blockIdx.x * 128;
        ncols = 512;
        Ap = g_o;
        Wp = h_wout;
    }

    uint32_t* const AsS[2] = { sm, sm + H_STAGE };
    uint32_t* const BsS[2] = { sm + 128 * HA_LD, sm + H_STAGE + 128 * HA_LD };

    float acc[2][8][4] = {};

#pragma unroll
    for (int i = 0; i < 2; i++) {
        const int idx = tid + i * 256;
        const int r = idx >> 2, q = idx & 3;
        CP16(smaddr(&AsS[0][r * HA_LD + q * 4]),
             Ap + (size_t)(row0 + r) * 512 + q * 8);
    }
#pragma unroll
    for (int i = 0; i < 2; i++) {
        const int idx = tid + i * 256;
        const int r = idx >> 4, q = idx & 15;
        CP16(smaddr(&BsS[0][r * HB_LD + q * 4]),
             Wp + (size_t)r * ncols + col0 + q * 8);
    }
    CPCOMMIT();

    for (int ch = 0; ch < 16; ch++) {
        CPWAIT0();
        __syncthreads();
        if (ch < 15) {
            const int k0 = (ch + 1) * 32;
            const int s  = (ch + 1) & 1;
#pragma unroll
            for (int i = 0; i < 2; i++) {
                const int idx = tid + i * 256;
                const int r = idx >> 2, q = idx & 3;
                CP16(smaddr(&AsS[s][r * HA_LD + q * 4]),
                     Ap + (size_t)(row0 + r) * 512 + k0 + q * 8);
            }
#pragma unroll
            for (int i = 0; i < 2; i++) {
                const int idx = tid + i * 256;
                const int r = idx >> 4, q = idx & 15;
                CP16(smaddr(&BsS[s][r * HB_LD + q * 4]),
                     Wp + (size_t)(k0 + r) * ncols + col0 + q * 8);
            }
            CPCOMMIT();
        }
        const uint32_t* as = AsS[ch & 1];
        const __half* bsh = reinterpret_cast<const __half*>(BsS[ch & 1]);

#pragma unroll
        for (int kt = 0; kt < 2; kt++) {
            uint32_t a[2][4];
#pragma unroll
            for (int mt = 0; mt < 2; mt++) {
                const int r = wr * 32 + mt * 16;
                a[mt][0] = as[(r + g) * HA_LD + kt * 8 + tg];
                a[mt][1] = as[(r + g + 8) * HA_LD + kt * 8 + tg];
                a[mt][2] = as[(r + g) * HA_LD + kt * 8 + tg + 4];
                a[mt][3] = as[(r + g + 8) * HA_LD + kt * 8 + tg + 4];
            }
            uint32_t bfr[8][2];
#pragma unroll
            for (int ntp = 0; ntp < 4; ntp++) {
                const int kr   = kt * 16 + ((lane >> 3) & 1) * 8 + (lane & 7);
                const int ncol = wc * 64 + (ntp * 2 + (lane >> 4)) * 8;
                ldsm4t(bfr[ntp * 2][0], bfr[ntp * 2][1],
                       bfr[ntp * 2 + 1][0], bfr[ntp * 2 + 1][1],
                       smaddr(&bsh[kr * (HB_LD * 2) + ncol]));
            }
#pragma unroll
            for (int nt = 0; nt < 8; nt++)
#pragma unroll
                for (int mt = 0; mt < 2; mt++)
                    mma_h(acc[mt][nt], a[mt][0], a[mt][1], a[mt][2], a[mt][3],
                          bfr[nt][0], bfr[nt][1]);
        }
    }

#pragma unroll
    for (int mt = 0; mt < 2; mt++) {
#pragma unroll
        for (int nt = 0; nt < 8; nt++) {
#pragma unroll
            for (int half = 0; half < 2; half++) {
                const int row = row0 + wr * 32 + mt * 16 + g + half * 8;
                const int col = col0 + wc * 64 + nt * 8 + 2 * tg;
                const float v0 = acc[mt][nt][half * 2 + 0];
                const float v1 = acc[mt][nt][half * 2 + 1];
                const int b = row >> 11, n = row & 2047;
                if (MODE == 3) {
                    __half* dst;
                    if (isQV) {
                        if (col < 512) {
                            const int h = col >> 6, d = col & 63;
                            dst = &g_q[((size_t)(b * 8 + h) * 2048 + n) * 64 + d];
                        } else {
                            const int c2 = col - 512;
                            const int h = c2 >> 6, d = c2 & 63;
                            dst = &g_v[((size_t)(b * 8 + h) * 2048 + n) * 64 + d];
                        }
                    } else {
                        const int h = col >> 6, d = col & 63;
                        dst = &g_k[((size_t)(b * 8 + h) * 2048 + n) * 64 + d];
                    }
                    *reinterpret_cast<uint32_t*>(dst) = pk(v0, v1);
                } else {
                    float* dst = &Cout[(size_t)row * 512 + col];
                    *reinterpret_cast<float2*>(dst) =
                        make_float2(v0 + bias[col], v1 + bias[col + 1]);
                }
            }
        }
    }
}

// ---------------------------------------------------------------------------
// Fused attention, fp16 MMA, 2-stage cp.async (round-7 proven config), with
// exp/PV interleaved per 16-row m-half so MUFU (ex2) overlaps tensor (PV MMA).
// smem u32: Qs[128][36] | Ks[2][32][36] | Vs[2][32][36] | Am[2][128][36]
//   = 18432 u32 = 73,728 B -> occupancy 2.
// ---------------------------------------------------------------------------
#define AQ_LD 36
#define ATT_SMEM_W (128 * AQ_LD + 4 * 32 * AQ_LD + 2 * 128 * AQ_LD)

__global__ void __launch_bounds__(256, 2)
attn_h(const float* __restrict__ amat,
       const float* __restrict__ dots_para,
       const float* __restrict__ mat_para)
{
    extern __shared__ uint32_t sm[];
    uint32_t* const Qs = sm;                              // 128*36
    uint32_t* const KsS[2] = { sm + 128 * AQ_LD, sm + 160 * AQ_LD };
    uint32_t* const VsS[2] = { sm + 192 * AQ_LD, sm + 224 * AQ_LD };
    uint32_t* const AmS[2] = { sm + 256 * AQ_LD, sm + 384 * AQ_LD };

    const int tid  = threadIdx.x;
    const int lane = tid & 31;
    const int w    = tid >> 5;
    const int g    = lane >> 2;
    const int tg   = lane & 3;
    const int b  = blockIdx.z, h = blockIdx.y;
    const int n0 = blockIdx.x * 128;

    const float qscale = 0.125f * dots_para[0] * 1.44269504f;
    const float mp = mat_para[0] * 1.44269504f;

    const size_t qbase  = ((size_t)(b * 8 + h) * 2048 + n0) * 64;
    const size_t kvbase = (size_t)(b * 8 + h) * 2048 * 64;
    const size_t abase  = ((size_t)(b * 8 + h) * 2048 + n0) * 2048;

    // Q (128x64 fp16) + K/V chunk 0 + amat chunk 0
#pragma unroll
    for (int i = 0; i < 4; i++) {
        const int idx = tid + i * 256;
        const int r = idx >> 3, q = idx & 7;
        CP16(smaddr(&Qs[r * AQ_LD + q * 4]), g_q + qbase + (size_t)r * 64 + q * 8);
    }
    {
        const int r = tid >> 3, q = tid & 7;
        CP16(smaddr(&KsS[0][r * AQ_LD + q * 4]), g_k + kvbase + (size_t)r * 64 + q * 8);
        CP16(smaddr(&VsS[0][r * AQ_LD + q * 4]), g_v + kvbase + (size_t)r * 64 + q * 8);
    }
#pragma unroll
    for (int i = 0; i < 4; i++) {
        const int idx = tid + i * 256;
        const int r = idx >> 3, c = (idx & 7) * 4;
        CP16(smaddr(&AmS[0][r * AQ_LD + c]), amat + abase + (size_t)r * 2048 + c);
    }
    CPCOMMIT();

    float O[8][4] = {};
    float rl0 = 0.f, rl1 = 0.f;
    const int rowA = w * 16 + g;

    for (int ch = 0; ch < 64; ch++) {
        CPWAIT0();
        __syncthreads();
        if (ch < 63) {
            const size_t m1 = (size_t)(ch + 1) * 32;
            const int s = (ch + 1) & 1;
            {
                const int r = tid >> 3, q = tid & 7;
                CP16(smaddr(&KsS[s][r * AQ_LD + q * 4]),
                     g_k + kvbase + (m1 + r) * 64 + q * 8);
                CP16(smaddr(&VsS[s][r * AQ_LD + q * 4]),
                     g_v + kvbase + (m1 + r) * 64 + q * 8);
            }
#pragma unroll
            for (int i = 0; i < 4; i++) {
                const int idx = tid + i * 256;
                const int r = idx >> 3, c = (idx & 7) * 4;
                CP16(smaddr(&AmS[s][r * AQ_LD + c]),
                     amat + abase + (size_t)r * 2048 + m1 + c);
            }
            CPCOMMIT();
        }
        const __half* Qsh = reinterpret_cast<const __half*>(Qs);
        const __half* Ksh = reinterpret_cast<const __half*>(KsS[ch & 1]);
        const __half* Vsh = reinterpret_cast<const __half*>(VsS[ch & 1]);
        const float*  Am  = reinterpret_cast<const float*>(AmS[ch & 1]);

        // S = Q @ K^T  (per warp 16 x 32), frags via ldmatrix.x4
        float S[4][4] = {};
#pragma unroll
        for (int kt = 0; kt < 4; kt++) {
            uint32_t aq0, aq1, aq2, aq3;
            {
                const int mr = w * 16 + (lane & 15);
                const int kc = kt * 16 + (lane >> 4) * 8;
                ldsm4(aq0, aq1, aq2, aq3, smaddr(&Qsh[mr * (AQ_LD * 2) + kc]));
            }
#pragma unroll
            for (int ntp = 0; ntp < 2; ntp++) {
                uint32_t kb0, kb1, kb2, kb3;
                const int nr = ntp * 16 + ((lane >> 4) & 1) * 8 + (lane & 7);
                const int kc = kt * 16 + ((lane >> 3) & 1) * 8;
                ldsm4(kb0, kb1, kb2, kb3, smaddr(&Ksh[nr * (AQ_LD * 2) + kc]));
                mma_h(S[ntp * 2],     aq0, aq1, aq2, aq3, kb0, kb1);
                mma_h(S[ntp * 2 + 1], aq0, aq1, aq2, aq3, kb2, kb3);
            }
        }

        // exp + PV interleaved per 16-row m-half: the j=1 exp chain (MUFU)
        // overlaps the j=0 PV MMAs (tensor pipe).
#pragma unroll
        for (int j = 0; j < 2; j++) {
            uint32_t pva[4];
#pragma unroll
            for (int t = 0; t < 2; t++) {
                const int nt = j * 2 + t;
                const int acol = nt * 8 + 2 * tg;
                const float2 amA = *reinterpret_cast<const float2*>(
                    &Am[rowA * AQ_LD + acol]);
                const float2 amB = *reinterpret_cast<const float2*>(
                    &Am[(rowA + 8) * AQ_LD + acol]);
                const float p0 = ex2f(S[nt][0] * qscale + amA.x * mp);
                const float p1 = ex2f(S[nt][1] * qscale + amA.y * mp);
                const float p2 = ex2f(S[nt][2] * qscale + amB.x * mp);
                const float p3 = ex2f(S[nt][3] * qscale + amB.y * mp);
                rl0 += p0 + p1;
                rl1 += p2 + p3;
                pva[t * 2 + 0] = pk(p0, p1);
                pva[t * 2 + 1] = pk(p2, p3);
            }
            uint32_t vb[8][2];
#pragma unroll
            for (int ntp = 0; ntp < 4; ntp++) {
                const int mr = j * 16 + ((lane >> 3) & 1) * 8 + (lane & 7);
                const int dc = (ntp * 2 + (lane >> 4)) * 8;
                ldsm4t(vb[ntp * 2][0], vb[ntp * 2][1],
                       vb[ntp * 2 + 1][0], vb[ntp * 2 + 1][1],
                       smaddr(&Vsh[mr * (AQ_LD * 2) + dc]));
            }
#pragma unroll
            for (int nt = 0; nt < 8; nt++)
                mma_h(O[nt], pva[0], pva[1], pva[2], pva[3],
                      vb[nt][0], vb[nt][1]);
        }
    }

    // quad-reduce row sums, normalize, store fp16
#pragma unroll
    for (int off = 1; off <= 2; off <<= 1) {
        rl0 += __shfl_xor_sync(0xffffffffu, rl0, off);
        rl1 += __shfl_xor_sync(0xffffffffu, rl1, off);
    }
    const float inv0 = 1.0f / rl0;
    const float inv1 = 1.0f / rl1;
    const int grow = n0 + rowA;
#pragma unroll
    for (int nt = 0; nt < 8; nt++) {
        const int col = h * 64 + nt * 8 + 2 * tg;
        *reinterpret_cast<uint32_t*>(&g_o[((size_t)b * 2048 + grow) * 512 + col]) =
            pk(O[nt][0] * inv0, O[nt][1] * inv0);
        *reinterpret_cast<uint32_t*>(&g_o[((size_t)b * 2048 + grow + 8) * 512 + col]) =
            pk(O[nt][2] * inv1, O[nt][3] * inv1);
    }
}

// ---------------------------------------------------------------------------
extern "C" void kernel_launch(void* const* d_in, const int* in_sizes, int n_in,
                              void* d_out, int out_size)
{
    const float* x    = (const float*)d_in[0];
    const float* x1   = (const float*)d_in[1];
    const float* amat = (const float*)d_in[2];
    const float* dp   = (const float*)d_in[3];
    const float* mp   = (const float*)d_in[4];
    const float* Wqv  = (const float*)d_in[5];
    const float* Wk   = (const float*)d_in[6];
    const float* Wout = (const float*)d_in[7];
    const float* bout = (const float*)d_in[8];
    float* out = (float*)d_out;

    const int gsmem = 2 * H_STAGE * (int)sizeof(uint32_t);   // 37,888 B
    const int asmem = ATT_SMEM_W * (int)sizeof(uint32_t);    // 73,728 B
    cudaFuncSetAttribute((const void*)attn_h,
                         cudaFuncAttributeMaxDynamicSharedMemorySize, asmem);

    // fp32 -> fp16 staging
    convert_k<<<dim3(2048, 5), 256>>>(x, x1, Wqv, Wk, Wout);
    // fused q,v,k projection: grid.x 0-7 -> qv cols, 8-11 -> k cols (384 CTAs)
    gemm_h<3><<<dim3(12, 32), 256, gsmem>>>(nullptr, nullptr);
    // fused attention
    attn_h<<<dim3(16, 8, 2), 256, asmem>>>(amat, dp, mp);
    // output projection + bias
    gemm_h<2><<<dim3(4, 32), 256, gsmem>>>(bout, out);
}